// round 5
// baseline (speedup 1.0000x reference)
#include <cuda_runtime.h>

// FourStateQuantizer: elementwise soft quantization over states {-1,-0.5,0.5,1}, T=0.3.
// softmax(-(x-s)^2/T): x^2 cancels -> w_i ∝ exp((2 s_i x - s_i^2)/T). With u = e^{x/T},
// multiply num/den by u^2 -> polynomials in u only:
//   q = [c2(u^4-1) + 0.5 c1 u(u^2-1)] / [c2(u^4+1) + c1 u(u^2+1)]
// Clamp x to [-6,6]: q(±6) = ±(1 - 1.2e-8); keeps u^4 finite.
// 2 MUFU/elem (EX2 + RCP-divide).
// R5: MLP=8 (8 front-batched LDG.128/thread) + streaming cache hints (__ldcs/__stcs).

__device__ __forceinline__ float quant1(float x) {
    const float K   = 4.80898346962988f;     // log2(e)/0.3
    const float C1H = 0.2172991042535391f;   // 0.5*exp(-0.25/0.3)
    const float C2  = 0.03567399334725241f;  // exp(-1.0/0.3)
    x = fminf(fmaxf(x, -6.0f), 6.0f);
    float u  = exp2f(x * K);                 // MUFU.EX2
    float u2 = u * u;
    float u4 = u2 * u2;
    float w1 = C1H * u;
    float w2 = w1 + w1;
    float num = fmaf(w1, u2 - 1.0f, fmaf(C2, u4, -C2));
    float den = fmaf(w2, u2 + 1.0f, fmaf(C2, u4,  C2));
    return __fdividef(num, den);             // MUFU.RCP + FMUL
}

__device__ __forceinline__ float4 quant4(float4 x) {
    float4 q;
    q.x = quant1(x.x); q.y = quant1(x.y);
    q.z = quant1(x.z); q.w = quant1(x.w);
    return q;
}

#define UNROLL 8

__global__ __launch_bounds__(256) void fourstate_kernel(
    const float4* __restrict__ in, float4* __restrict__ out, int n4)
{
    int base = blockIdx.x * (256 * UNROLL) + threadIdx.x;
    if (base + (UNROLL - 1) * 256 < n4) {
        // fast path (exact for this problem size): 8 front-batched loads -> MLP_p1=8
        float4 x[UNROLL];
        #pragma unroll
        for (int j = 0; j < UNROLL; j++)
            x[j] = __ldcs(&in[base + j * 256]);
        float4 q[UNROLL];
        #pragma unroll
        for (int j = 0; j < UNROLL; j++)
            q[j] = quant4(x[j]);
        #pragma unroll
        for (int j = 0; j < UNROLL; j++)
            __stcs(&out[base + j * 256], q[j]);
    } else {
        #pragma unroll
        for (int j = 0; j < UNROLL; j++) {
            int i = base + j * 256;
            if (i < n4) __stcs(&out[i], quant4(__ldcs(&in[i])));
        }
    }
}

extern "C" void kernel_launch(void* const* d_in, const int* in_sizes, int n_in,
                              void* d_out, int out_size) {
    const float4* in = (const float4*)d_in[0];
    float4* out = (float4*)d_out;
    int n  = in_sizes[0];               // 50,331,648
    int n4 = n >> 2;                    // 12,582,912 float4s
    int per_block = 256 * UNROLL;       // 2048 float4s per block
    int blocks = (n4 + per_block - 1) / per_block;   // 6144, exact
    fourstate_kernel<<<blocks, 256>>>(in, out, n4);
}